// round 16
// baseline (speedup 1.0000x reference)
#include <cuda_runtime.h>
#include <cstdint>

// L2 access policy: evict_last (keep the 64MB values table resident in L2
// against the 512MB streaming W read).
__device__ __forceinline__ unsigned long long make_evict_last_policy() {
    unsigned long long pol;
    asm volatile("createpolicy.fractional.L2::evict_last.b64 %0, 1.0;" : "=l"(pol));
    return pol;
}

// Scalar gather load, L2-resident via cache-hint policy. Winner shape:
// the 16 lanes of one LDG cover one contiguous 64B values row (1 wavefront).
__device__ __forceinline__ float ldg_L2_resident(const float* p, unsigned long long pol) {
    float v;
    asm volatile("ld.global.nc.L2::cache_hint.f32 %0, [%1], %2;"
                 : "=f"(v) : "l"(p), "l"(pol));
    return v;
}

// One neuron per 16 threads. lane = element index d in [0,16).
//   s[d]  = sum_k values[idx[n,k]*16 + d]   (coalesced 64B gathers, L2-pinned)
//   y[d]  = b[n,d] + sum_j W[n,d,j] * s[j]  (s[j] via shfl width 16)
//   out   = tanh(y)
// idx dtype (int32 vs int64) detected inline from the first 32 bytes of idx:
// uniform-address __ldg loads (broadcast; ~free). For int64 indices in
// [0,1e6) the odd 32-bit words are all 0; for random int32, 4 odd words all
// zero has probability ~1e-24.
__global__ __launch_bounds__(128)
void weighted_atom_kernel(const float* __restrict__ values,
                          const void*  __restrict__ idx_raw,
                          const float* __restrict__ W,
                          const float* __restrict__ bvec,
                          float* __restrict__ out,
                          int N)
{
    const int gid  = blockIdx.x * blockDim.x + threadIdx.x;
    const int n    = gid >> 4;
    const int lane = gid & 15;
    if (n >= N) return;   // grid sized exactly; never taken (keeps shfl safe)

    const unsigned long long pol = make_evict_last_policy();

    // ---- inline dtype detect (uniform loads, grid-wide same address) ----
    const int4* head = (const int4*)idx_raw;
    int4 h0 = __ldg(head + 0);
    int4 h1 = __ldg(head + 1);
    const bool is64 = ((h0.y | h0.w | h1.y | h1.w) == 0);

    // ---- fetch the 8 fan-in row indices (values < 2^20 -> int is exact) ----
    int rows[8];
    if (is64) {
        // 8 x int64 = 64B = 4 x int4; keep only the low words
        const int4* p = (const int4*)((const long long*)idx_raw + (long long)n * 8);
        int4 q0 = p[0], q1 = p[1], q2 = p[2], q3 = p[3];
        rows[0] = q0.x; rows[1] = q0.z;
        rows[2] = q1.x; rows[3] = q1.z;
        rows[4] = q2.x; rows[5] = q2.z;
        rows[6] = q3.x; rows[7] = q3.z;
    } else {
        // 8 x int32 = 32B = 2 x int4
        const int4* p = (const int4*)((const int*)idx_raw + n * 8);
        int4 q0 = p[0], q1 = p[1];
        rows[0] = q0.x; rows[1] = q0.y; rows[2] = q0.z; rows[3] = q0.w;
        rows[4] = q1.x; rows[5] = q1.y; rows[6] = q1.z; rows[7] = q1.w;
    }

    // ---- streaming loads of W (4 x LDG.128, evict-first) + b ----
    const float4* Wrow4 = (const float4*)(W + (size_t)n * 256 + (size_t)lane * 16);
    float4 w0 = __ldcs(Wrow4 + 0);
    float4 w1 = __ldcs(Wrow4 + 1);
    float4 w2 = __ldcs(Wrow4 + 2);
    float4 w3 = __ldcs(Wrow4 + 3);
    float  y  = __ldcs(bvec + gid);   // b[n*16 + lane]

    // ---- gather + fan-in sum: lane d owns element d; L2-resident ----
    float s = 0.0f;
    #pragma unroll
    for (int k = 0; k < 8; ++k) {
        s += ldg_L2_resident(values + (unsigned)(rows[k] * 16 + lane), pol);
    }

    const unsigned mask = 0xFFFFFFFFu;
    y += w0.x * __shfl_sync(mask, s,  0, 16);
    y += w0.y * __shfl_sync(mask, s,  1, 16);
    y += w0.z * __shfl_sync(mask, s,  2, 16);
    y += w0.w * __shfl_sync(mask, s,  3, 16);
    y += w1.x * __shfl_sync(mask, s,  4, 16);
    y += w1.y * __shfl_sync(mask, s,  5, 16);
    y += w1.z * __shfl_sync(mask, s,  6, 16);
    y += w1.w * __shfl_sync(mask, s,  7, 16);
    y += w2.x * __shfl_sync(mask, s,  8, 16);
    y += w2.y * __shfl_sync(mask, s,  9, 16);
    y += w2.z * __shfl_sync(mask, s, 10, 16);
    y += w2.w * __shfl_sync(mask, s, 11, 16);
    y += w3.x * __shfl_sync(mask, s, 12, 16);
    y += w3.y * __shfl_sync(mask, s, 13, 16);
    y += w3.z * __shfl_sync(mask, s, 14, 16);
    y += w3.w * __shfl_sync(mask, s, 15, 16);

    __stcs(out + gid, tanhf(y));
}

extern "C" void kernel_launch(void* const* d_in, const int* in_sizes, int n_in,
                              void* d_out, int out_size)
{
    // metadata order == setup_inputs order: values, idx, W, b
    const float* values = (const float*)d_in[0];
    const void*  idx    = d_in[1];
    const float* W      = (const float*)d_in[2];
    const float* bvec   = (const float*)d_in[3];
    float* out          = (float*)d_out;

    const int N = in_sizes[3] / 16;   // b has N*16 elements

    const int threads = 128;          // 8 groups per block; finer CTA granularity
    const int total   = N * 16;
    const int blocks  = (total + threads - 1) / threads;
    weighted_atom_kernel<<<blocks, threads>>>(values, idx, W, bvec, out, N);
}

// round 17
// speedup vs baseline: 1.0149x; 1.0149x over previous
#include <cuda_runtime.h>
#include <cstdint>

// L2 access policy: evict_last (keep the 64MB values table resident in L2
// against the 512MB streaming W read).
__device__ __forceinline__ unsigned long long make_evict_last_policy() {
    unsigned long long pol;
    asm volatile("createpolicy.fractional.L2::evict_last.b64 %0, 1.0;" : "=l"(pol));
    return pol;
}

// Scalar gather load, L2-resident via cache-hint policy. Winner shape:
// the 16 lanes of one LDG cover one contiguous 64B values row (1 wavefront).
__device__ __forceinline__ float ldg_L2_resident(const float* p, unsigned long long pol) {
    float v;
    asm volatile("ld.global.nc.L2::cache_hint.f32 %0, [%1], %2;"
                 : "=f"(v) : "l"(p), "l"(pol));
    return v;
}

// One neuron per 16 threads. lane = element index d in [0,16).
//   s[d]  = sum_k values[idx[n,k]*16 + d]   (coalesced 64B gathers, L2-pinned)
//   y[d]  = b[n,d] + sum_j W[n,d,j] * s[j]  (s[j] via shfl width 16)
//   out   = tanh(y)
// idx dtype (int32 vs int64) detected inline from the first 32 bytes of idx:
// uniform-address __ldg loads (broadcast; ~free). For int64 indices in
// [0,1e6) the odd 32-bit words are all 0; for random int32, 4 odd words all
// zero has probability ~1e-24.
__global__ __launch_bounds__(256)
void weighted_atom_kernel(const float* __restrict__ values,
                          const void*  __restrict__ idx_raw,
                          const float* __restrict__ W,
                          const float* __restrict__ bvec,
                          float* __restrict__ out,
                          int N)
{
    const int gid  = blockIdx.x * blockDim.x + threadIdx.x;
    const int n    = gid >> 4;
    const int lane = gid & 15;
    if (n >= N) return;   // grid sized exactly; never taken (keeps shfl safe)

    const unsigned long long pol = make_evict_last_policy();

    // ---- inline dtype detect (uniform loads, grid-wide same address) ----
    const int4* head = (const int4*)idx_raw;
    int4 h0 = __ldg(head + 0);
    int4 h1 = __ldg(head + 1);
    const bool is64 = ((h0.y | h0.w | h1.y | h1.w) == 0);

    // ---- fetch the 8 fan-in row indices with vector loads ----
    long long rows[8];
    if (is64) {
        // 8 x int64 = 64B = 4 x int4 (uniform across the 16-lane group)
        const int4* p = (const int4*)((const long long*)idx_raw + (long long)n * 8);
        int4 q0 = p[0], q1 = p[1], q2 = p[2], q3 = p[3];
        rows[0] = ((long long)q0.y << 32) | (unsigned int)q0.x;
        rows[1] = ((long long)q0.w << 32) | (unsigned int)q0.z;
        rows[2] = ((long long)q1.y << 32) | (unsigned int)q1.x;
        rows[3] = ((long long)q1.w << 32) | (unsigned int)q1.z;
        rows[4] = ((long long)q2.y << 32) | (unsigned int)q2.x;
        rows[5] = ((long long)q2.w << 32) | (unsigned int)q2.z;
        rows[6] = ((long long)q3.y << 32) | (unsigned int)q3.x;
        rows[7] = ((long long)q3.w << 32) | (unsigned int)q3.z;
    } else {
        // 8 x int32 = 32B = 2 x int4
        const int4* p = (const int4*)((const int*)idx_raw + n * 8);
        int4 q0 = p[0], q1 = p[1];
        rows[0] = q0.x; rows[1] = q0.y; rows[2] = q0.z; rows[3] = q0.w;
        rows[4] = q1.x; rows[5] = q1.y; rows[6] = q1.z; rows[7] = q1.w;
    }

    // ---- streaming loads of W (4 x LDG.128, evict-first) + b ----
    const float4* Wrow4 = (const float4*)(W + (size_t)n * 256 + (size_t)lane * 16);
    float4 w0 = __ldcs(Wrow4 + 0);
    float4 w1 = __ldcs(Wrow4 + 1);
    float4 w2 = __ldcs(Wrow4 + 2);
    float4 w3 = __ldcs(Wrow4 + 3);
    float  y  = __ldcs(bvec + gid);   // b[n*16 + lane]

    // ---- gather + fan-in sum: lane d owns element d; L2-resident ----
    float s = 0.0f;
    #pragma unroll
    for (int k = 0; k < 8; ++k) {
        s += ldg_L2_resident(values + rows[k] * 16 + lane, pol);
    }

    const unsigned mask = 0xFFFFFFFFu;
    y += w0.x * __shfl_sync(mask, s,  0, 16);
    y += w0.y * __shfl_sync(mask, s,  1, 16);
    y += w0.z * __shfl_sync(mask, s,  2, 16);
    y += w0.w * __shfl_sync(mask, s,  3, 16);
    y += w1.x * __shfl_sync(mask, s,  4, 16);
    y += w1.y * __shfl_sync(mask, s,  5, 16);
    y += w1.z * __shfl_sync(mask, s,  6, 16);
    y += w1.w * __shfl_sync(mask, s,  7, 16);
    y += w2.x * __shfl_sync(mask, s,  8, 16);
    y += w2.y * __shfl_sync(mask, s,  9, 16);
    y += w2.z * __shfl_sync(mask, s, 10, 16);
    y += w2.w * __shfl_sync(mask, s, 11, 16);
    y += w3.x * __shfl_sync(mask, s, 12, 16);
    y += w3.y * __shfl_sync(mask, s, 13, 16);
    y += w3.z * __shfl_sync(mask, s, 14, 16);
    y += w3.w * __shfl_sync(mask, s, 15, 16);

    __stcs(out + gid, tanhf(y));
}

extern "C" void kernel_launch(void* const* d_in, const int* in_sizes, int n_in,
                              void* d_out, int out_size)
{
    // metadata order == setup_inputs order: values, idx, W, b
    const float* values = (const float*)d_in[0];
    const void*  idx    = d_in[1];
    const float* W      = (const float*)d_in[2];
    const float* bvec   = (const float*)d_in[3];
    float* out          = (float*)d_out;

    const int N = in_sizes[3] / 16;   // b has N*16 elements

    const int threads = 256;
    const int total   = N * 16;
    const int blocks  = (total + threads - 1) / threads;
    weighted_atom_kernel<<<blocks, threads>>>(values, idx, W, bvec, out, N);
}